// round 2
// baseline (speedup 1.0000x reference)
#include <cuda_runtime.h>
#include <math.h>

// Problem dims
#define HD    2048      // hidden
#define NE    8         // experts
#define NI    1408      // expert intermediate
#define NI2   2816      // 2*NI
#define NSI   2816      // shared intermediate
#define NSI2  5632      // 2*NSI
#define NT    8192      // tokens
#define NPAIR 16384     // NT * top_k

// Scratch (device globals; shared-expert and expert phases reuse them since
// they are stream-ordered):  NPAIR*NI2 == NT*NSI2 == 46137344,
//                            NPAIR*NI  == NT*NSI  == 23068672
__device__ float g_Y[46137344];
__device__ float g_ACT[23068672];
__device__ int   g_cnt[NE];
__device__ int   g_list[NE * NT];
__device__ float g_w[NPAIR];

__global__ void reset_kernel() {
    if (threadIdx.x < NE) g_cnt[threadIdx.x] = 0;
}

// One warp per token: 8 logits, softmax, top-2, renormalize, build routing lists.
__global__ void gate_kernel(const float* __restrict__ x, const float* __restrict__ gw) {
    int t = blockIdx.x * 8 + threadIdx.y;
    int lane = threadIdx.x;
    const float* xr = x + (size_t)t * HD;
    float p[NE];
#pragma unroll
    for (int e = 0; e < NE; e++) {
        float s = 0.f;
        const float* wr = gw + e * HD;
        for (int k = lane; k < HD; k += 32) s += xr[k] * wr[k];
#pragma unroll
        for (int o = 16; o; o >>= 1) s += __shfl_xor_sync(0xffffffffu, s, o);
        p[e] = s;
    }
    float mx = p[0];
#pragma unroll
    for (int e = 1; e < NE; e++) mx = fmaxf(mx, p[e]);
    float den = 0.f;
#pragma unroll
    for (int e = 0; e < NE; e++) { p[e] = expf(p[e] - mx); den += p[e]; }
    // top-2, ties -> lowest index (strict > while scanning ascending)
    int i1 = 0;
#pragma unroll
    for (int e = 1; e < NE; e++) if (p[e] > p[i1]) i1 = e;
    int i2 = (i1 == 0) ? 1 : 0;
#pragma unroll
    for (int e = 0; e < NE; e++) if (e != i1 && p[e] > p[i2]) i2 = e;

    float s1 = p[i1] / den, s2 = p[i2] / den;
    float rs = s1 + s2 + 1e-20f;
    if (lane == 0) {
        g_w[2 * t]     = s1 / rs;
        g_w[2 * t + 1] = s2 / rs;
        int a = atomicAdd(&g_cnt[i1], 1); g_list[i1 * NT + a] = 2 * t;
        int b = atomicAdd(&g_cnt[i2], 1); g_list[i2 * NT + b] = 2 * t + 1;
    }
}

// C[M,N] = A[M,K] @ B[N,K]^T, 128x128x8 tiles, 8x8 per thread.
// Register-prefetch pipeline: tile k+1 is fetched from GMEM into registers
// while tile k is being computed from SMEM, hiding LDG latency.
// MODE 0: direct rows, plain store                        (shared-expert GEMMs)
// MODE 1: A row = list[m]>>1 (token), C row = list[m]     (expert GEMM1, gathered)
// MODE 2: A row = list[m], atomicAdd w*val to out[token]  (expert GEMM2, scatter)
template <int MODE>
__global__ void __launch_bounds__(256, 2)
gemm_nt(const float* __restrict__ Abase, const float* __restrict__ Bbase,
        float* __restrict__ Cbase, int N, int K)
{
    const int BM = 128, BN = 128, BK = 8;
    int M;
    const int* list = nullptr;
    const float* B = Bbase;
    if (MODE == 1 || MODE == 2) {
        int e = blockIdx.z;
        M = g_cnt[e];
        list = g_list + e * NT;
        B = Bbase + (size_t)e * (size_t)N * (size_t)K;
    } else {
        M = NT;
    }
    int m0 = blockIdx.x * BM, n0 = blockIdx.y * BN;
    if (m0 >= M) return;   // early-exit for fixed worst-case grid

    __shared__ __align__(16) float As[BK][BM];
    __shared__ __align__(16) float Bs[BK][BN];

    int tid  = threadIdx.x;
    int arow = tid >> 1;            // 0..127, also B tile row
    int ak   = (tid & 1) * 4;       // 0 or 4

    bool avalid = (m0 + arow) < M;
    const float* Ap = Abase;        // dummy init (never dereferenced when !avalid)
    if (avalid) {
        if (MODE == 0) {
            Ap = Abase + (size_t)(m0 + arow) * K + ak;
        } else {
            int rid = list[m0 + arow];
            int ar  = (MODE == 1) ? (rid >> 1) : rid;
            Ap = Abase + (size_t)ar * K + ak;
        }
    }
    const float* Bp = B + (size_t)(n0 + arow) * K + ak;

    int tm = tid >> 4, tn = tid & 15;
    float acc[8][8];
#pragma unroll
    for (int i = 0; i < 8; i++)
#pragma unroll
        for (int j = 0; j < 8; j++) acc[i][j] = 0.f;

    // Prologue: fetch tile 0 into registers.
    float4 av = make_float4(0.f, 0.f, 0.f, 0.f);
    if (avalid) av = *(const float4*)(Ap);
    float4 bv = *(const float4*)(Bp);

    for (int k0 = 0; k0 < K; k0 += BK) {
        __syncthreads();
        As[ak + 0][arow] = av.x; As[ak + 1][arow] = av.y;
        As[ak + 2][arow] = av.z; As[ak + 3][arow] = av.w;
        Bs[ak + 0][arow] = bv.x; Bs[ak + 1][arow] = bv.y;
        Bs[ak + 2][arow] = bv.z; Bs[ak + 3][arow] = bv.w;
        __syncthreads();

        // Prefetch next tile while computing this one.
        int k1 = k0 + BK;
        if (k1 < K) {
            av = make_float4(0.f, 0.f, 0.f, 0.f);
            if (avalid) av = *(const float4*)(Ap + k1);
            bv = *(const float4*)(Bp + k1);
        }

#pragma unroll
        for (int kk = 0; kk < BK; kk++) {
            float4 a0 = *(const float4*)&As[kk][tm * 8];
            float4 a1 = *(const float4*)&As[kk][tm * 8 + 4];
            float4 b0 = *(const float4*)&Bs[kk][tn * 8];
            float4 b1 = *(const float4*)&Bs[kk][tn * 8 + 4];
            float ar8[8] = {a0.x, a0.y, a0.z, a0.w, a1.x, a1.y, a1.z, a1.w};
            float br8[8] = {b0.x, b0.y, b0.z, b0.w, b1.x, b1.y, b1.z, b1.w};
#pragma unroll
            for (int i = 0; i < 8; i++)
#pragma unroll
                for (int j = 0; j < 8; j++)
                    acc[i][j] = fmaf(ar8[i], br8[j], acc[i][j]);
        }
    }

#pragma unroll
    for (int i = 0; i < 8; i++) {
        int m = m0 + tm * 8 + i;
        if (m >= M) continue;
        if (MODE == 2) {
            int r = list[m];
            int tok = r >> 1;
            float w = g_w[r];
            float* cr = Cbase + (size_t)tok * N + n0 + tn * 8;
#pragma unroll
            for (int j = 0; j < 8; j++) atomicAdd(cr + j, w * acc[i][j]);
        } else {
            size_t crow = (MODE == 1) ? (size_t)list[m] : (size_t)m;
            float* cr = Cbase + crow * N + n0 + tn * 8;
            *(float4*)(cr)     = make_float4(acc[i][0], acc[i][1], acc[i][2], acc[i][3]);
            *(float4*)(cr + 4) = make_float4(acc[i][4], acc[i][5], acc[i][6], acc[i][7]);
        }
    }
}

// act[r, c] = silu(y[r, c]) * y[r, inner + c]
__global__ void silu_mul_kernel(const float* __restrict__ y, float* __restrict__ a, int inner) {
    int c = blockIdx.x * blockDim.x + threadIdx.x;
    int r = blockIdx.y;
    if (c >= inner) return;
    size_t base = (size_t)r * 2 * inner;
    float g  = y[base + c];
    float pr = y[base + inner + c];
    float s = g / (1.f + expf(-g));
    a[(size_t)r * inner + c] = s * pr;
}

extern "C" void kernel_launch(void* const* d_in, const int* in_sizes, int n_in,
                              void* d_out, int out_size) {
    const float* x   = (const float*)d_in[0];   // [T, H]
    const float* gw  = (const float*)d_in[1];   // [E, H]
    const float* ewg = (const float*)d_in[2];   // [E, 2I, H]
    const float* ewd = (const float*)d_in[3];   // [E, H, I]
    const float* swg = (const float*)d_in[4];   // [2SI, H]
    const float* swd = (const float*)d_in[5];   // [H, SI]
    float* out = (float*)d_out;                 // [T, H]

    float* Yp;  float* Ap;
    cudaGetSymbolAddress((void**)&Yp, g_Y);
    cudaGetSymbolAddress((void**)&Ap, g_ACT);

    // Routing
    reset_kernel<<<1, 32>>>();
    gate_kernel<<<NT / 8, dim3(32, 8)>>>(x, gw);

    // Shared expert (plain-stores the full output, initializing d_out)
    gemm_nt<0><<<dim3(NT / 128, NSI2 / 128, 1), 256>>>(x, swg, Yp, NSI2, HD);
    silu_mul_kernel<<<dim3((NSI + 255) / 256, NT), 256>>>(Yp, Ap, NSI);
    gemm_nt<0><<<dim3(NT / 128, HD / 128, 1), 256>>>(Ap, swd, out, HD, NSI);

    // Routed experts (atomicAdd on top of shared-expert result)
    gemm_nt<1><<<dim3(NT / 128, NI2 / 128, NE), 256>>>(x, ewg, Yp, NI2, HD);
    silu_mul_kernel<<<dim3((NI + 255) / 256, NPAIR), 256>>>(Yp, Ap, NI);
    gemm_nt<2><<<dim3(NT / 128, HD / 128, NE), 256>>>(Ap, ewd, out, HD, NI);
}

// round 13
// speedup vs baseline: 2.5433x; 2.5433x over previous
#include <cuda_runtime.h>
#include <cuda_bf16.h>
#include <cstdint>
#include <stddef.h>
#include <math.h>

// ---------------- Problem dims ----------------
#define HD    2048
#define NE    8
#define NI    1408
#define NSI   2816
#define NT    8192
#define NPAIR 16384
#define NPAD  17408   // NPAIR + NE*128: compact 128-aligned expert rows bound

// ---------------- Device scratch (~98 MB) ----------------
__device__ float g_act[(size_t)NPAD * NI];
__device__ int   g_cnt[NE];
__device__ int   g_off[NE + 1];
__device__ int   g_list[NE * NT];
__device__ float g_w[NPAIR];

// ---------------- helpers ----------------
__device__ __forceinline__ uint32_t smem_u32(const void* p) {
    uint32_t a;
    asm("{ .reg .u64 t; cvta.to.shared.u64 t, %1; cvt.u32.u64 %0, t; }" : "=r"(a) : "l"(p));
    return a;
}
__device__ __forceinline__ void ldsm_x4(uint32_t a[4], uint32_t addr) {
    asm volatile("ldmatrix.sync.aligned.m8n8.x4.shared.b16 {%0,%1,%2,%3}, [%4];"
        : "=r"(a[0]), "=r"(a[1]), "=r"(a[2]), "=r"(a[3]) : "r"(addr));
}
__device__ __forceinline__ void ldsm_x2(uint32_t a[2], uint32_t addr) {
    asm volatile("ldmatrix.sync.aligned.m8n8.x2.shared.b16 {%0,%1}, [%2];"
        : "=r"(a[0]), "=r"(a[1]) : "r"(addr));
}
__device__ __forceinline__ void mma_bf16(float c[4], const uint32_t a[4], const uint32_t b[2]) {
    asm volatile("mma.sync.aligned.m16n8k16.row.col.f32.bf16.bf16.f32 "
        "{%0,%1,%2,%3}, {%4,%5,%6,%7}, {%8,%9}, {%0,%1,%2,%3};"
        : "+f"(c[0]), "+f"(c[1]), "+f"(c[2]), "+f"(c[3])
        : "r"(a[0]), "r"(a[1]), "r"(a[2]), "r"(a[3]), "r"(b[0]), "r"(b[1]));
}
// SW128 swizzle inside a [rows][64 bf16] tile: 128B rows, kb = 16B chunk 0..7.
__device__ __forceinline__ uint32_t sw(int r, int kb) {
    return (uint32_t)(r * 128 + ((kb * 16) ^ ((r & 7) * 16)));
}
// fp32x4 -> (hi bf16, lo bf16) to two swizzled smem tiles at byte offsets tH/tL.
__device__ __forceinline__ void cvt_st(char* smem, int tH, int tL, int r, int cc, float4 v) {
    __nv_bfloat16 hx = __float2bfloat16_rn(v.x), hy = __float2bfloat16_rn(v.y);
    __nv_bfloat16 hz = __float2bfloat16_rn(v.z), hw = __float2bfloat16_rn(v.w);
    __nv_bfloat162 h01(hx, hy), h23(hz, hw);
    __nv_bfloat162 l01(__float2bfloat16_rn(v.x - __bfloat162float(hx)),
                       __float2bfloat16_rn(v.y - __bfloat162float(hy)));
    __nv_bfloat162 l23(__float2bfloat16_rn(v.z - __bfloat162float(hz)),
                       __float2bfloat16_rn(v.w - __bfloat162float(hw)));
    uint32_t off = (uint32_t)(r * 128 + (((cc >> 1) << 4) ^ ((r & 7) << 4)) + ((cc & 1) << 3));
    *(uint2*)(smem + tH + off) = make_uint2(*(uint32_t*)&h01, *(uint32_t*)&h23);
    *(uint2*)(smem + tL + off) = make_uint2(*(uint32_t*)&l01, *(uint32_t*)&l23);
}

// ---------------- routing ----------------
__global__ void reset_kernel() { if (threadIdx.x < NE) g_cnt[threadIdx.x] = 0; }

__global__ void gate_kernel(const float* __restrict__ x, const float* __restrict__ gw) {
    int t = blockIdx.x * 8 + threadIdx.y;
    int lane = threadIdx.x;
    const float* xr = x + (size_t)t * HD;
    float p[NE];
#pragma unroll
    for (int e = 0; e < NE; e++) {
        float s = 0.f;
        const float* wr = gw + e * HD;
        for (int k = lane; k < HD; k += 32) s += xr[k] * wr[k];
#pragma unroll
        for (int o = 16; o; o >>= 1) s += __shfl_xor_sync(0xffffffffu, s, o);
        p[e] = s;
    }
    float mx = p[0];
#pragma unroll
    for (int e = 1; e < NE; e++) mx = fmaxf(mx, p[e]);
    float den = 0.f;
#pragma unroll
    for (int e = 0; e < NE; e++) { p[e] = expf(p[e] - mx); den += p[e]; }
    int i1 = 0;
#pragma unroll
    for (int e = 1; e < NE; e++) if (p[e] > p[i1]) i1 = e;
    int i2 = (i1 == 0) ? 1 : 0;
#pragma unroll
    for (int e = 0; e < NE; e++) if (e != i1 && p[e] > p[i2]) i2 = e;
    float s1 = p[i1] / den, s2 = p[i2] / den;
    float rs = s1 + s2 + 1e-20f;
    if (lane == 0) {
        g_w[2 * t] = s1 / rs; g_w[2 * t + 1] = s2 / rs;
        int a = atomicAdd(&g_cnt[i1], 1); g_list[i1 * NT + a] = 2 * t;
        int b = atomicAdd(&g_cnt[i2], 1); g_list[i2 * NT + b] = 2 * t + 1;
    }
}

__global__ void finalize_kernel() {
    if (threadIdx.x == 0) {
        int o = 0;
        g_off[0] = 0;
        for (int e = 0; e < NE; e++) {
            o += ((g_cnt[e] + 127) >> 7) << 7;
            g_off[e + 1] = o;
        }
    }
}

// ---------------- GEMM1: fused gate+up+silu (HMMA, 3-term bf16 split) --------
// ACT[m,n] = silu(X@WgT[m,n]) * (X@WgT[m,I+n]).  CTA tile 64m x 64n, 8 warps
// (2m x 4n), each 32m x 16n for BOTH gate and proj accumulators.
// Smem (48KB exactly, no attribute opt-in needed):
//   Ah 0, Al 8K, Bgh 16K, Bgl 24K, Bph 32K, Bpl 40K   (all [64 rows][128B])
#define SM1 49152
#define SM2 49152

template <int MODE>
__global__ void __launch_bounds__(256, 2)
mm1(const float* __restrict__ X, const float* __restrict__ Wg,
    float* __restrict__ ACT, int I)
{
    const int KC = HD / 64;
    int e = blockIdx.z;
    int m0 = blockIdx.x * 64, n0 = blockIdx.y * 64;
    int M, orow0;
    const float* Wb = Wg;
    if (MODE == 0) { M = NT; orow0 = m0; }
    else { M = g_cnt[e]; if (m0 >= M) return; orow0 = g_off[e] + m0;
           Wb = Wg + (size_t)e * 2 * I * HD; }

    extern __shared__ __align__(1024) char smem[];
    uint32_t sb = smem_u32(smem);
    int tid = threadIdx.x, wid = tid >> 5, lane = tid & 31;
    int tr = tid >> 4, cc = tid & 15;

    int arow[4];
#pragma unroll
    for (int j = 0; j < 4; j++) {
        int r = tr + 16 * j;
        if (MODE == 0) arow[j] = m0 + r;
        else { int i = m0 + r; if (i >= M) i = M - 1; arow[j] = g_list[e * NT + i] >> 1; }
    }
    int wm = wid & 1, wn = wid >> 1;          // 2m x 4n warps

    float accg[2][2][4], accp[2][2][4];
#pragma unroll
    for (int a = 0; a < 2; a++)
#pragma unroll
        for (int b = 0; b < 2; b++)
#pragma unroll
            for (int d = 0; d < 4; d++) { accg[a][b][d] = 0.f; accp[a][b][d] = 0.f; }

    for (int c = 0; c < KC; c++) {
        int k0 = c * 64;
        __syncthreads();
#pragma unroll
        for (int j = 0; j < 4; j++) {
            int r = tr + 16 * j;
            cvt_st(smem, 0,     8192,  r, cc, *(const float4*)(X  + (size_t)arow[j] * HD + k0 + cc * 4));
            cvt_st(smem, 16384, 24576, r, cc, *(const float4*)(Wb + (size_t)(n0 + r) * HD + k0 + cc * 4));
            cvt_st(smem, 32768, 40960, r, cc, *(const float4*)(Wb + (size_t)(I + n0 + r) * HD + k0 + cc * 4));
        }
        __syncthreads();
#pragma unroll
        for (int kk = 0; kk < 4; kk++) {
            uint32_t ah[2][4], al[2][4];
#pragma unroll
            for (int mt = 0; mt < 2; mt++) {
                int row = wm * 32 + mt * 16 + (lane & 7) + ((lane >> 3) & 1) * 8;
                int kb = 2 * kk + (lane >> 4);
                ldsm_x4(ah[mt], sb + sw(row, kb));
                ldsm_x4(al[mt], sb + 8192 + sw(row, kb));
            }
#pragma unroll
            for (int nt = 0; nt < 2; nt++) {
                int Le = lane & 15;
                int row = wn * 16 + nt * 8 + (Le & 7);
                int kb = 2 * kk + (Le >> 3);
                uint32_t bh[2], bl[2];
                ldsm_x2(bh, sb + 16384 + sw(row, kb));
                ldsm_x2(bl, sb + 24576 + sw(row, kb));
#pragma unroll
                for (int mt = 0; mt < 2; mt++) {
                    mma_bf16(accg[mt][nt], ah[mt], bh);
                    mma_bf16(accg[mt][nt], al[mt], bh);
                    mma_bf16(accg[mt][nt], ah[mt], bl);
                }
                ldsm_x2(bh, sb + 32768 + sw(row, kb));
                ldsm_x2(bl, sb + 40960 + sw(row, kb));
#pragma unroll
                for (int mt = 0; mt < 2; mt++) {
                    mma_bf16(accp[mt][nt], ah[mt], bh);
                    mma_bf16(accp[mt][nt], al[mt], bh);
                    mma_bf16(accp[mt][nt], ah[mt], bl);
                }
            }
        }
    }
    // epilogue: silu(gate)*proj -> fp32 ACT
#pragma unroll
    for (int mt = 0; mt < 2; mt++)
#pragma unroll
        for (int h = 0; h < 2; h++) {
            int lr = wm * 32 + mt * 16 + (lane >> 2) + h * 8;
            if (m0 + lr < M) {
                float* dst = ACT + (size_t)(orow0 + lr) * I + n0 + wn * 16 + 2 * (lane & 3);
#pragma unroll
                for (int nt = 0; nt < 2; nt++) {
                    float g0 = accg[mt][nt][2 * h], g1 = accg[mt][nt][2 * h + 1];
                    float p0 = accp[mt][nt][2 * h], p1 = accp[mt][nt][2 * h + 1];
                    float2 o;
                    o.x = (g0 / (1.f + expf(-g0))) * p0;
                    o.y = (g1 / (1.f + expf(-g1))) * p1;
                    *(float2*)(dst + nt * 8) = o;
                }
            }
        }
}

// ---------------- GEMM2: down-proj ----------------
// OUT[m, HD] (+)= ACT[m, K] @ Wd[HD, K]^T.  CTA 128m x 64n, 8 warps (4m x 2n).
// Smem (48KB): Ah 0, Al 16K, Bh 32K, Bl 40K.
template <int MODE>
__global__ void __launch_bounds__(256, 2)
mm2(const float* __restrict__ A, const float* __restrict__ Wd,
    float* __restrict__ OUT, int K)
{
    const int KC = K / 64;
    int e = blockIdx.z;
    int m0 = blockIdx.x * 128, n0 = blockIdx.y * 64;
    int M, abase;
    const float* Wb = Wd;
    if (MODE == 0) { M = NT; abase = 0; }
    else { M = g_cnt[e]; if (m0 >= M) return; abase = g_off[e];
           Wb = Wd + (size_t)e * HD * NI; }

    extern __shared__ __align__(1024) char smem[];
    uint32_t sb = smem_u32(smem);
    int tid = threadIdx.x, wid = tid >> 5, lane = tid & 31;
    int tr = tid >> 4, cc = tid & 15;

    int arow[8];
#pragma unroll
    for (int j = 0; j < 8; j++) {
        int r = tr + 16 * j;
        int i = m0 + r; if (i >= M) i = M - 1;
        arow[j] = abase + i;
    }
    int wm = wid & 3, wn = wid >> 2;

    float acc[2][4][4];
#pragma unroll
    for (int a = 0; a < 2; a++)
#pragma unroll
        for (int b = 0; b < 4; b++)
#pragma unroll
            for (int d = 0; d < 4; d++) acc[a][b][d] = 0.f;

    for (int c = 0; c < KC; c++) {
        int k0 = c * 64;
        __syncthreads();
#pragma unroll
        for (int j = 0; j < 8; j++) {
            int r = tr + 16 * j;
            cvt_st(smem, 0, 16384, r, cc, *(const float4*)(A + (size_t)arow[j] * K + k0 + cc * 4));
        }
#pragma unroll
        for (int j = 0; j < 4; j++) {
            int r = tr + 16 * j;
            cvt_st(smem, 32768, 40960, r, cc, *(const float4*)(Wb + (size_t)(n0 + r) * K + k0 + cc * 4));
        }
        __syncthreads();
#pragma unroll
        for (int kk = 0; kk < 4; kk++) {
            uint32_t ah[2][4], al[2][4];
#pragma unroll
            for (int mt = 0; mt < 2; mt++) {
                int row = wm * 32 + mt * 16 + (lane & 7) + ((lane >> 3) & 1) * 8;
                int kb = 2 * kk + (lane >> 4);
                ldsm_x4(ah[mt], sb + sw(row, kb));
                ldsm_x4(al[mt], sb + 16384 + sw(row, kb));
            }
#pragma unroll
            for (int nt = 0; nt < 4; nt++) {
                int Le = lane & 15;
                int row = wn * 32 + nt * 8 + (Le & 7);
                int kb = 2 * kk + (Le >> 3);
                uint32_t bh[2], bl[2];
                ldsm_x2(bh, sb + 32768 + sw(row, kb));
                ldsm_x2(bl, sb + 40960 + sw(row, kb));
#pragma unroll
                for (int mt = 0; mt < 2; mt++) {
                    mma_bf16(acc[mt][nt], ah[mt], bh);
                    mma_bf16(acc[mt][nt], al[mt], bh);
                    mma_bf16(acc[mt][nt], ah[mt], bl);
                }
            }
        }
    }
#pragma unroll
    for (int mt = 0; mt < 2; mt++)
#pragma unroll
        for (int h = 0; h < 2; h++) {
            int i = m0 + wm * 32 + mt * 16 + (lane >> 2) + h * 8;
            if (i >= M) continue;
            if (MODE == 0) {
                float* dst = OUT + (size_t)i * HD + n0 + wn * 32 + 2 * (lane & 3);
#pragma unroll
                for (int nt = 0; nt < 4; nt++) {
                    float2 o = make_float2(acc[mt][nt][2 * h], acc[mt][nt][2 * h + 1]);
                    *(float2*)(dst + nt * 8) = o;
                }
            } else {
                int rid = g_list[e * NT + i];
                int tok = rid >> 1;
                float w = g_w[rid];
                float* dst = OUT + (size_t)tok * HD + n0 + wn * 32 + 2 * (lane & 3);
#pragma unroll
                for (int nt = 0; nt < 4; nt++) {
                    atomicAdd(dst + nt * 8,     w * acc[mt][nt][2 * h]);
                    atomicAdd(dst + nt * 8 + 1, w * acc[mt][nt][2 * h + 1]);
                }
            }
        }
}

// ---------------- host (NO cudaFuncSetAttribute anywhere) ----------------
extern "C" void kernel_launch(void* const* d_in, const int* in_sizes, int n_in,
                              void* d_out, int out_size) {
    const float* x   = (const float*)d_in[0];
    const float* gw  = (const float*)d_in[1];
    const float* ewg = (const float*)d_in[2];
    const float* ewd = (const float*)d_in[3];
    const float* swg = (const float*)d_in[4];
    const float* swd = (const float*)d_in[5];
    float* out = (float*)d_out;

    void* act;
    cudaGetSymbolAddress(&act, g_act);

    // routing
    reset_kernel<<<1, 32>>>();
    gate_kernel<<<NT / 8, dim3(32, 8)>>>(x, gw);
    finalize_kernel<<<1, 32>>>();

    // shared expert: fused gate/up+silu, then down-proj (plain store inits out)
    mm1<0><<<dim3(NT / 64, NSI / 64, 1), 256, SM1>>>(x, swg, (float*)act, NSI);
    mm2<0><<<dim3(NT / 128, HD / 64, 1), 256, SM2>>>((const float*)act, swd, out, NSI);

    // routed experts (worst-case grid, early-exit on counts), weighted scatter
    mm1<1><<<dim3(NT / 64, NI / 64, NE), 256, SM1>>>(x, ewg, (float*)act, NI);
    mm2<2><<<dim3(NT / 128, HD / 64, NE), 256, SM2>>>((const float*)act, ewd, out, NI);
}